// round 13
// baseline (speedup 1.0000x reference)
#include <cuda_runtime.h>
#include <cuda_bf16.h>
#include <math.h>

#define BB 2
#define TT 2048
#define EE 512
#define NHH 8
#define HDD 64
#define BHH (BB*NHH)
#define E3 (3*EE)
// SCALE * log2(e): folded into Q at fill time -> QK output is in log2 units
#define QSC 0.18033688011112042f
// EPS for masked columns: 2^-60. All-masked rows normalize to exactly 1/T.
#define MASK_EPS 0x1.0p-60f

// Scratch (no allocations allowed)
__device__ float g_qkv[(size_t)BB * TT * E3];    // 25 MB
__device__ float g_params[(size_t)BHH * TT * 6];
__device__ float g_attn[(size_t)BB * TT * EE];   // 8 MB

// ---------------------------------------------------------------------------
// helpers
// ---------------------------------------------------------------------------
__device__ __forceinline__ unsigned f2tf32(float x) {
    unsigned r; asm("cvt.rna.tf32.f32 %0, %1;" : "=r"(r) : "f"(x)); return r;
}
// bf16 hi/lo split of (x,y): h = bf16x2(lo=x, hi=y), l = residual pair
__device__ __forceinline__ void split2_bf16(float x, float y, unsigned& h, unsigned& l) {
    __nv_bfloat16 hx = __float2bfloat16(x);
    __nv_bfloat16 hy = __float2bfloat16(y);
    float rx = x - __bfloat162float(hx);
    float ry = y - __bfloat162float(hy);
    __nv_bfloat16 lx = __float2bfloat16(rx);
    __nv_bfloat16 ly = __float2bfloat16(ry);
    h = ((unsigned)__bfloat16_as_ushort(hy) << 16) | (unsigned)__bfloat16_as_ushort(hx);
    l = ((unsigned)__bfloat16_as_ushort(ly) << 16) | (unsigned)__bfloat16_as_ushort(lx);
}
__device__ __forceinline__ void mma_tf32(
    float& d0, float& d1, float& d2, float& d3,
    unsigned a0, unsigned a1, unsigned a2, unsigned a3,
    unsigned b0, unsigned b1)
{
    asm("mma.sync.aligned.m16n8k8.row.col.f32.tf32.tf32.f32 "
        "{%0,%1,%2,%3}, {%4,%5,%6,%7}, {%8,%9}, {%0,%1,%2,%3};"
        : "+f"(d0), "+f"(d1), "+f"(d2), "+f"(d3)
        : "r"(a0), "r"(a1), "r"(a2), "r"(a3), "r"(b0), "r"(b1));
}
__device__ __forceinline__ void mma_bf16(
    float& d0, float& d1, float& d2, float& d3,
    unsigned a0, unsigned a1, unsigned a2, unsigned a3,
    unsigned b0, unsigned b1)
{
    asm("mma.sync.aligned.m16n8k16.row.col.f32.bf16.bf16.f32 "
        "{%0,%1,%2,%3}, {%4,%5,%6,%7}, {%8,%9}, {%0,%1,%2,%3};"
        : "+f"(d0), "+f"(d1), "+f"(d2), "+f"(d3)
        : "r"(a0), "r"(a1), "r"(a2), "r"(a3), "r"(b0), "r"(b1));
}

// ---------------------------------------------------------------------------
// bf16x3 GEMM, BK=32: C[M,N] = A[M,K] @ W[K,N] + bias.
// BM=128, BN=64, BK=32 (16 k-pairs, 2 k16-slices). 256 threads = 8 warps
// (4m x 2n), warp tile m32 x n32. 48 MMAs per barrier pair (was 24).
// Accumulation order per accumulator identical to the BK=16 version.
// ---------------------------------------------------------------------------
__global__ __launch_bounds__(256, 2) void gemm_bias_kernel(
    const float* __restrict__ A, const float* __restrict__ W,
    const float* __restrict__ bias, float* __restrict__ C,
    int M, int N, int K)
{
    __shared__ unsigned Ah[16 * 136];  // [kpair][m] bf16x2
    __shared__ unsigned Al[16 * 136];
    __shared__ unsigned Bh[16 * 72];   // [kpair][n] bf16x2
    __shared__ unsigned Bl[16 * 72];

    int bm = blockIdx.y * 128;
    int bn = blockIdx.x * 64;
    int tid = threadIdx.x;
    int warp = tid >> 5, lane = tid & 31;
    int wm = warp >> 1, wn = warp & 1;
    int lq = lane >> 2, lr = lane & 3;

    float acc[2][4][4];
#pragma unroll
    for (int mt = 0; mt < 2; mt++)
#pragma unroll
        for (int nt = 0; nt < 4; nt++)
#pragma unroll
            for (int c = 0; c < 4; c++) acc[mt][nt][c] = 0.f;

    int am = tid >> 1, akp = (tid & 1) * 8;   // A: row am, kpairs akp..akp+7
    int bk2 = tid >> 4, bc4 = (tid & 15) * 4; // B: kpair bk2 (0..15), cols bc4..+3

    const float* Ap  = A + (size_t)(bm + am) * K + akp * 2;
    const float* Wp0 = W + (size_t)(2 * bk2) * N + bn + bc4;
    const float* Wp1 = Wp0 + N;

    float4 av0 = *(const float4*)(Ap);
    float4 av1 = *(const float4*)(Ap + 4);
    float4 av2 = *(const float4*)(Ap + 8);
    float4 av3 = *(const float4*)(Ap + 12);
    float4 wv0 = *(const float4*)(Wp0);
    float4 wv1 = *(const float4*)(Wp1);

    for (int k0 = 0; k0 < K; k0 += 32) {
        __syncthreads();
        {
            float av[16] = {av0.x, av0.y, av0.z, av0.w, av1.x, av1.y, av1.z, av1.w,
                            av2.x, av2.y, av2.z, av2.w, av3.x, av3.y, av3.z, av3.w};
#pragma unroll
            for (int c = 0; c < 8; c++) {
                unsigned h, l;
                split2_bf16(av[2 * c], av[2 * c + 1], h, l);
                Ah[(akp + c) * 136 + am] = h;
                Al[(akp + c) * 136 + am] = l;
            }
            unsigned h, l;
            split2_bf16(wv0.x, wv1.x, h, l);
            Bh[bk2 * 72 + bc4]     = h; Bl[bk2 * 72 + bc4]     = l;
            split2_bf16(wv0.y, wv1.y, h, l);
            Bh[bk2 * 72 + bc4 + 1] = h; Bl[bk2 * 72 + bc4 + 1] = l;
            split2_bf16(wv0.z, wv1.z, h, l);
            Bh[bk2 * 72 + bc4 + 2] = h; Bl[bk2 * 72 + bc4 + 2] = l;
            split2_bf16(wv0.w, wv1.w, h, l);
            Bh[bk2 * 72 + bc4 + 3] = h; Bl[bk2 * 72 + bc4 + 3] = l;
        }
        __syncthreads();

        if (k0 + 32 < K) {
            av0 = *(const float4*)(Ap + k0 + 32);
            av1 = *(const float4*)(Ap + k0 + 36);
            av2 = *(const float4*)(Ap + k0 + 40);
            av3 = *(const float4*)(Ap + k0 + 44);
            wv0 = *(const float4*)(Wp0 + (size_t)(k0 + 32) * N);
            wv1 = *(const float4*)(Wp1 + (size_t)(k0 + 32) * N);
        }

#pragma unroll
        for (int ks = 0; ks < 2; ks++) {
            int kb = ks * 8;
            unsigned ah[2][4], al_[2][4];
#pragma unroll
            for (int mt = 0; mt < 2; mt++) {
                int mb = wm * 32 + mt * 16 + lq;
                ah[mt][0]  = Ah[(kb + lr) * 136 + mb];
                ah[mt][1]  = Ah[(kb + lr) * 136 + mb + 8];
                ah[mt][2]  = Ah[(kb + lr + 4) * 136 + mb];
                ah[mt][3]  = Ah[(kb + lr + 4) * 136 + mb + 8];
                al_[mt][0] = Al[(kb + lr) * 136 + mb];
                al_[mt][1] = Al[(kb + lr) * 136 + mb + 8];
                al_[mt][2] = Al[(kb + lr + 4) * 136 + mb];
                al_[mt][3] = Al[(kb + lr + 4) * 136 + mb + 8];
            }
#pragma unroll
            for (int nt = 0; nt < 4; nt++) {
                int nb = wn * 32 + nt * 8 + lq;
                unsigned bh0 = Bh[(kb + lr) * 72 + nb];
                unsigned bh1 = Bh[(kb + lr + 4) * 72 + nb];
                unsigned bl0 = Bl[(kb + lr) * 72 + nb];
                unsigned bl1 = Bl[(kb + lr + 4) * 72 + nb];
#pragma unroll
                for (int mt = 0; mt < 2; mt++) {
                    mma_bf16(acc[mt][nt][0], acc[mt][nt][1], acc[mt][nt][2], acc[mt][nt][3],
                             ah[mt][0], ah[mt][1], ah[mt][2], ah[mt][3], bh0, bh1);
                    mma_bf16(acc[mt][nt][0], acc[mt][nt][1], acc[mt][nt][2], acc[mt][nt][3],
                             ah[mt][0], ah[mt][1], ah[mt][2], ah[mt][3], bl0, bl1);
                    mma_bf16(acc[mt][nt][0], acc[mt][nt][1], acc[mt][nt][2], acc[mt][nt][3],
                             al_[mt][0], al_[mt][1], al_[mt][2], al_[mt][3], bh0, bh1);
                }
            }
        }
    }

#pragma unroll
    for (int mt = 0; mt < 2; mt++) {
        int row = bm + wm * 32 + mt * 16 + lq;
#pragma unroll
        for (int nt = 0; nt < 4; nt++) {
            int col = bn + wn * 32 + nt * 8 + 2 * lr;
            float bv0 = bias[col], bv1 = bias[col + 1];
            float2 o0, o1;
            o0.x = acc[mt][nt][0] + bv0; o0.y = acc[mt][nt][1] + bv1;
            o1.x = acc[mt][nt][2] + bv0; o1.y = acc[mt][nt][3] + bv1;
            *(float2*)&C[(size_t)row * N + col] = o0;
            *(float2*)&C[(size_t)(row + 8) * N + col] = o1;
        }
    }
}

// ---------------------------------------------------------------------------
// od kernel: warp per (b,t) row, w_od staged in smem.
// ---------------------------------------------------------------------------
__global__ __launch_bounds__(256) void od_kernel(
    const float* __restrict__ w_od, const float* __restrict__ b_od)
{
    __shared__ float ws[EE * 16];  // 32 KB
    int tid = threadIdx.x;
#pragma unroll
    for (int i = 0; i < 8; i++) {
        int idx = (i * 256 + tid) * 4;
        *(float4*)&ws[idx] = *(const float4*)&w_od[idx];
    }
    __syncthreads();

    int warp = tid >> 5, lane = tid & 31;
    int bt = blockIdx.x * 8 + warp;
    int b = bt / TT, t = bt % TT;
    const float* qrow = g_qkv + (size_t)bt * E3;

    int c = lane & 15, hseg = lane >> 4;
    float acc = 0.f;
#pragma unroll 8
    for (int kk = 0; kk < 256; kk++) {
        int k = 2 * kk + hseg;
        acc = fmaf(qrow[k], ws[k * 16 + c], acc);
    }
    acc += __shfl_xor_sync(0xffffffffu, acc, 16);
    float odm = acc + b_od[c];
    float odp = __shfl_sync(0xffffffffu, odm, (lane & 7) + 8);

    if (lane < 8) {
        int h = lane;
        float off = tanhf(odm) * (float)TT;
        float dur = (float)TT / (1.f + expf(-odp));
        float anchor = (float)t + off;
        float start = anchor - dur;
        float end   = anchor + dur;
        float blv = floorf(start);
        float brv = ceilf(end);
        float alv = floorf(anchor);
        float frv = anchor - alv;
        float* p = g_params + ((size_t)(b * NHH + h) * TT + t) * 6;
        p[0] = blv;
        p[1] = brv;
        p[2] = blv - start;
        p[3] = end - brv;
        p[4] = alv;
        p[5] = frv;
    }
}

// ---------------------------------------------------------------------------
// Tensor-core flash deformable attention, shift-free softmax (R12).
// CTA: 128 queries, 8 warps (warp = 16 q rows), j-tiles of 64, 2 CTAs/SM.
// Q pre-scaled by SCALE*log2e -> QK output in log2 units; p = exp2(t*w).
// QK: 1x tf32. PV: bf16x3 (R7 interleaved products).
// ---------------------------------------------------------------------------
#define QS_S 68
#define VS_S 72
__global__ __launch_bounds__(256, 2) void attn_kernel()
{
    extern __shared__ unsigned smu[];
    unsigned* Qs = smu;                  // [128 q][QS_S] tf32; reused as P (fp32)
    float*   Psf = (float*)smu;          // overlay
    unsigned* Ks = Qs + 128 * QS_S;      // [64 j][QS_S] tf32
    unsigned* Vh = Ks + 64 * QS_S;       // [32 jpair][VS_S] bf16x2 hi
    unsigned* Vl = Vh + 32 * VS_S;       // [32 jpair][VS_S] bf16x2 lo
    float*    Pp = (float*)(Vl + 32 * VS_S); // [128][8] params
    __shared__ int s_jt0, s_jt1;

    int qt = blockIdx.x;
    int bh = blockIdx.y;
    int b = bh >> 3, h = bh & 7;
    int tid = threadIdx.x;
    int warp = tid >> 5, lane = tid & 31;
    int lq = lane >> 2, lr = lane & 3;
    int q0 = qt * 128;

    // Q fill (tf32, pre-scaled by SCALE*log2e)
    const float* qbase = g_qkv + ((size_t)(b * TT) + q0) * E3 + h * HDD;
#pragma unroll
    for (int it = 0; it < 8; it++) {
        int idx = it * 256 + tid;
        int r = idx >> 4, c4 = idx & 15;
        float4 v = *(const float4*)&qbase[(size_t)r * E3 + c4 * 4];
        uint4 u;
        u.x = f2tf32(v.x * QSC); u.y = f2tf32(v.y * QSC);
        u.z = f2tf32(v.z * QSC); u.w = f2tf32(v.w * QSC);
        *(uint4*)&Qs[r * QS_S + c4 * 4] = u;
    }
    // params
    if (tid < 128) {
        const float* p = g_params + ((size_t)bh * TT + q0 + tid) * 6;
#pragma unroll
        for (int c = 0; c < 6; c++) Pp[tid * 8 + c] = p[c];
        float lo = fmaxf(p[0], 0.f);
        float hi = fminf(p[1], (float)(TT - 1));
        Pp[tid * 8 + 6] = lo;
        Pp[tid * 8 + 7] = hi;
    }
    __syncthreads();
    if (tid == 0) {
        float jmin = 1e30f, jmax = -1e30f;
        int empty = 0;
        for (int r = 0; r < 128; r++) {
            float lo = Pp[r * 8 + 6], hi = Pp[r * 8 + 7];
            if (lo > hi) empty = 1;
            jmin = fminf(jmin, lo);
            jmax = fmaxf(jmax, hi);
        }
        if (empty) { s_jt0 = 0; s_jt1 = TT - 1; }
        else       { s_jt0 = ((int)jmin) & ~63; s_jt1 = (int)jmax; }
    }
    __syncthreads();

    int lr0 = warp * 16 + lq;
    int lr1 = lr0 + 8;
    float bl0 = Pp[lr0 * 8 + 0], br0 = Pp[lr0 * 8 + 1];
    float wbl0 = Pp[lr0 * 8 + 2], wbr0 = Pp[lr0 * 8 + 3];
    float al0 = Pp[lr0 * 8 + 4], fr0 = Pp[lr0 * 8 + 5];
    float bl1 = Pp[lr1 * 8 + 0], br1 = Pp[lr1 * 8 + 1];
    float wbl1 = Pp[lr1 * 8 + 2], wbr1 = Pp[lr1 * 8 + 3];
    float al1 = Pp[lr1 * 8 + 4], fr1 = Pp[lr1 * 8 + 5];
    float fa0 = 1.f - fr0, ar0 = al0 + 1.f;
    float fa1 = 1.f - fr1, ar1 = al1 + 1.f;

    // Q a-frags (persistent; smem Q is overwritten by P later)
    unsigned qa[8][4];
#pragma unroll
    for (int kt = 0; kt < 8; kt++) {
        qa[kt][0] = Qs[lr0 * QS_S + kt * 8 + lr];
        qa[kt][1] = Qs[lr1 * QS_S + kt * 8 + lr];
        qa[kt][2] = Qs[lr0 * QS_S + kt * 8 + lr + 4];
        qa[kt][3] = Qs[lr1 * QS_S + kt * 8 + lr + 4];
    }

    float l0 = 0.f, l1 = 0.f;   // per-thread partial row sums
    float o[8][4];
#pragma unroll
    for (int nt = 0; nt < 8; nt++)
#pragma unroll
        for (int c = 0; c < 4; c++) o[nt][c] = 0.f;

    const float* kbase = g_qkv + (size_t)(b * TT) * E3 + EE + h * HDD;
    const float* vbase = g_qkv + (size_t)(b * TT) * E3 + 2 * EE + h * HDD;
    int jt0 = s_jt0, jt1 = s_jt1;

    for (int jt = jt0; jt <= jt1; jt += 64) {
        __syncthreads();
        // K fill (tf32 1x)
#pragma unroll
        for (int it = 0; it < 4; it++) {
            int idx = it * 256 + tid;
            int r = idx >> 4, c4 = idx & 15;
            float4 kv = *(const float4*)&kbase[(size_t)(jt + r) * E3 + c4 * 4];
            uint4 ku;
            ku.x = f2tf32(kv.x); ku.y = f2tf32(kv.y); ku.z = f2tf32(kv.z); ku.w = f2tf32(kv.w);
            *(uint4*)&Ks[r * QS_S + c4 * 4] = ku;
        }
        // V fill: bf16x2 packed across j pairs, hi/lo split
        {
            int r2 = tid >> 3, c8 = (tid & 7) * 8;  // jpair r2, cols c8..c8+7
            const float* v0p = &vbase[(size_t)(jt + 2 * r2) * E3 + c8];
            const float* v1p = &vbase[(size_t)(jt + 2 * r2 + 1) * E3 + c8];
            float4 v0a = *(const float4*)(v0p);
            float4 v0b = *(const float4*)(v0p + 4);
            float4 v1a = *(const float4*)(v1p);
            float4 v1b = *(const float4*)(v1p + 4);
            float r0v[8] = {v0a.x, v0a.y, v0a.z, v0a.w, v0b.x, v0b.y, v0b.z, v0b.w};
            float r1v[8] = {v1a.x, v1a.y, v1a.z, v1a.w, v1b.x, v1b.y, v1b.z, v1b.w};
#pragma unroll
            for (int cc = 0; cc < 8; cc++) {
                unsigned hv, lv;
                split2_bf16(r0v[cc], r1v[cc], hv, lv);
                Vh[r2 * VS_S + c8 + cc] = hv;
                Vl[r2 * VS_S + c8 + cc] = lv;
            }
        }
        __syncthreads();

        // S = Q @ K^T (m16 x n64 per warp, tf32; output in log2 units)
        float s[8][4];
#pragma unroll
        for (int nt = 0; nt < 8; nt++)
#pragma unroll
            for (int c = 0; c < 4; c++) s[nt][c] = 0.f;
#pragma unroll
        for (int kt = 0; kt < 8; kt++) {
#pragma unroll
            for (int nt = 0; nt < 8; nt++) {
                unsigned b0 = Ks[(nt * 8 + lq) * QS_S + kt * 8 + lr];
                unsigned b1 = Ks[(nt * 8 + lq) * QS_S + kt * 8 + lr + 4];
                mma_tf32(s[nt][0], s[nt][1], s[nt][2], s[nt][3],
                         qa[kt][0], qa[kt][1], qa[kt][2], qa[kt][3], b0, b1);
            }
        }

        // weights + mask + exp2 (no shift; masked -> EPS)
#pragma unroll
        for (int nt = 0; nt < 8; nt++) {
            float jf0 = (float)(jt + nt * 8 + 2 * lr);
            float jf1 = jf0 + 1.f;
            float p0, p1, p2, p3;
            {
                float w = 1.f;
                if (jf0 == bl0) w += wbl0;
                if (jf0 == br0) w += wbr0;
                if (jf0 == al0) w += fa0;
                if (jf0 == ar0) w += fr0;
                p0 = (jf0 < bl0 || jf0 > br0) ? MASK_EPS : exp2f(s[nt][0] * w);
            }
            {
                float w = 1.f;
                if (jf1 == bl0) w += wbl0;
                if (jf1 == br0) w += wbr0;
                if (jf1 == al0) w += fa0;
                if (jf1 == ar0) w += fr0;
                p1 = (jf1 < bl0 || jf1 > br0) ? MASK_EPS : exp2f(s[nt][1] * w);
            }
            {
                float w = 1.f;
                if (jf0 == bl1) w += wbl1;
                if (jf0 == br1) w += wbr1;
                if (jf0 == al1) w += fa1;
                if (jf0 == ar1) w += fr1;
                p2 = (jf0 < bl1 || jf0 > br1) ? MASK_EPS : exp2f(s[nt][2] * w);
            }
            {
                float w = 1.f;
                if (jf1 == bl1) w += wbl1;
                if (jf1 == br1) w += wbr1;
                if (jf1 == al1) w += fa1;
                if (jf1 == ar1) w += fr1;
                p3 = (jf1 < bl1 || jf1 > br1) ? MASK_EPS : exp2f(s[nt][3] * w);
            }
            l0 += p0 + p1;
            l1 += p2 + p3;
            float2 w0; w0.x = p0; w0.y = p1;
            float2 w1; w1.x = p2; w1.y = p3;
            *(float2*)&Psf[lr0 * QS_S + nt * 8 + 2 * lr] = w0;
            *(float2*)&Psf[lr1 * QS_S + nt * 8 + 2 * lr] = w1;
        }
        __syncwarp();

        // O += P @ V (bf16x3, R7 interleaved products) — no rescaling needed
#pragma unroll
        for (int kt = 0; kt < 4; kt++) {   // 16-j slices
            float2 p0 = *(const float2*)&Psf[lr0 * QS_S + kt * 16 + 2 * lr];
            float2 p1 = *(const float2*)&Psf[lr1 * QS_S + kt * 16 + 2 * lr];
            float2 p2 = *(const float2*)&Psf[lr0 * QS_S + kt * 16 + 8 + 2 * lr];
            float2 p3 = *(const float2*)&Psf[lr1 * QS_S + kt * 16 + 8 + 2 * lr];
            unsigned ph0, pl0, ph1, pl1, ph2, pl2, ph3, pl3;
            split2_bf16(p0.x, p0.y, ph0, pl0);
            split2_bf16(p1.x, p1.y, ph1, pl1);
            split2_bf16(p2.x, p2.y, ph2, pl2);
            split2_bf16(p3.x, p3.y, ph3, pl3);
#pragma unroll
            for (int nt = 0; nt < 8; nt++) {
                int nb = nt * 8 + lq;
                unsigned bh0 = Vh[(kt * 8 + lr) * VS_S + nb];
                unsigned bh1 = Vh[(kt * 8 + lr + 4) * VS_S + nb];
                unsigned bl0v = Vl[(kt * 8 + lr) * VS_S + nb];
                unsigned bl1v = Vl[(kt * 8 + lr + 4) * VS_S + nb];
                mma_bf16(o[nt][0], o[nt][1], o[nt][2], o[nt][3],
                         ph0, ph1, ph2, ph3, bh0, bh1);
                mma_bf16(o[nt][0], o[nt][1], o[nt][2], o[nt][3],
                         ph0, ph1, ph2, ph3, bl0v, bl1v);
                mma_bf16(o[nt][0], o[nt][1], o[nt][2], o[nt][3],
                         pl0, pl1, pl2, pl3, bh0, bh1);
            }
        }
    }

    // final row-sum reduction across the 4 threads of each row group
#pragma unroll
    for (int off = 1; off <= 2; off <<= 1) {
        l0 += __shfl_xor_sync(0xffffffffu, l0, off);
        l1 += __shfl_xor_sync(0xffffffffu, l1, off);
    }
    float inv0 = 1.f / l0, inv1 = 1.f / l1;
    float* ob = g_attn + ((size_t)(b * TT) + q0) * EE + h * HDD;
#pragma unroll
    for (int nt = 0; nt < 8; nt++) {
        int col = nt * 8 + 2 * lr;
        float2 v0, v1;
        v0.x = o[nt][0] * inv0; v0.y = o[nt][1] * inv0;
        v1.x = o[nt][2] * inv1; v1.y = o[nt][3] * inv1;
        *(float2*)&ob[(size_t)lr0 * EE + col] = v0;
        *(float2*)&ob[(size_t)lr1 * EE + col] = v1;
    }
}

#define ATTN_SMEM ((128*QS_S + 64*QS_S + 2*32*VS_S + 128*8) * 4)

// ---------------------------------------------------------------------------
extern "C" void kernel_launch(void* const* d_in, const int* in_sizes, int n_in,
                              void* d_out, int out_size)
{
    const float* x      = (const float*)d_in[0];
    const float* w_qkv  = (const float*)d_in[1];
    const float* b_qkv  = (const float*)d_in[2];
    const float* w_od   = (const float*)d_in[3];
    const float* b_od   = (const float*)d_in[4];
    const float* w_out  = (const float*)d_in[5];
    const float* b_out  = (const float*)d_in[6];
    float* out = (float*)d_out;

    float* qkv;  cudaGetSymbolAddress((void**)&qkv,  g_qkv);
    float* attn; cudaGetSymbolAddress((void**)&attn, g_attn);

    static int init = 0;
    if (!init) {
        init = 1;
        cudaFuncSetAttribute(attn_kernel,
                             cudaFuncAttributeMaxDynamicSharedMemorySize, ATTN_SMEM);
    }

    // 1) QKV = x @ w_qkv + b_qkv : (4096,512)@(512,1536), bf16x3, BK=32
    gemm_bias_kernel<<<dim3(E3 / 64, (BB * TT) / 128), 256>>>(
        x, w_qkv, b_qkv, qkv, BB * TT, E3, EE);

    // 2) window params (fp32)
    od_kernel<<<(BB * TT) / 8, 256>>>(w_od, b_od);

    // 3) tensor-core flash deformable attention (shift-free softmax)
    attn_kernel<<<dim3(TT / 128, BHH), 256, ATTN_SMEM>>>();

    // 4) out = attn @ w_out + b_out : (4096,512)@(512,512), bf16x3, BK=32
    gemm_bias_kernel<<<dim3(EE / 64, (BB * TT) / 128), 256>>>(
        attn, w_out, b_out, out, BB * TT, EE, EE);
}

// round 14
// speedup vs baseline: 1.0341x; 1.0341x over previous
#include <cuda_runtime.h>
#include <cuda_bf16.h>
#include <math.h>

#define BB 2
#define TT 2048
#define EE 512
#define NHH 8
#define HDD 64
#define BHH (BB*NHH)
#define E3 (3*EE)
// SCALE * log2(e): folded into Q at fill time -> QK output is in log2 units
#define QSC 0.18033688011112042f
// EPS for masked columns: 2^-60. All-masked rows normalize to exactly 1/T.
#define MASK_EPS 0x1.0p-60f

// Scratch (no allocations allowed)
__device__ float g_qkv[(size_t)BB * TT * E3];    // 25 MB
__device__ float g_params[(size_t)BHH * TT * 6];
__device__ float g_attn[(size_t)BB * TT * EE];   // 8 MB

// ---------------------------------------------------------------------------
// helpers
// ---------------------------------------------------------------------------
__device__ __forceinline__ unsigned f2tf32(float x) {
    unsigned r; asm("cvt.rna.tf32.f32 %0, %1;" : "=r"(r) : "f"(x)); return r;
}
__device__ __forceinline__ void split2_bf16(float x, float y, unsigned& h, unsigned& l) {
    __nv_bfloat16 hx = __float2bfloat16(x);
    __nv_bfloat16 hy = __float2bfloat16(y);
    float rx = x - __bfloat162float(hx);
    float ry = y - __bfloat162float(hy);
    __nv_bfloat16 lx = __float2bfloat16(rx);
    __nv_bfloat16 ly = __float2bfloat16(ry);
    h = ((unsigned)__bfloat16_as_ushort(hy) << 16) | (unsigned)__bfloat16_as_ushort(hx);
    l = ((unsigned)__bfloat16_as_ushort(ly) << 16) | (unsigned)__bfloat16_as_ushort(lx);
}
__device__ __forceinline__ void mma_tf32(
    float& d0, float& d1, float& d2, float& d3,
    unsigned a0, unsigned a1, unsigned a2, unsigned a3,
    unsigned b0, unsigned b1)
{
    asm("mma.sync.aligned.m16n8k8.row.col.f32.tf32.tf32.f32 "
        "{%0,%1,%2,%3}, {%4,%5,%6,%7}, {%8,%9}, {%0,%1,%2,%3};"
        : "+f"(d0), "+f"(d1), "+f"(d2), "+f"(d3)
        : "r"(a0), "r"(a1), "r"(a2), "r"(a3), "r"(b0), "r"(b1));
}
__device__ __forceinline__ void mma_bf16(
    float& d0, float& d1, float& d2, float& d3,
    unsigned a0, unsigned a1, unsigned a2, unsigned a3,
    unsigned b0, unsigned b1)
{
    asm("mma.sync.aligned.m16n8k16.row.col.f32.bf16.bf16.f32 "
        "{%0,%1,%2,%3}, {%4,%5,%6,%7}, {%8,%9}, {%0,%1,%2,%3};"
        : "+f"(d0), "+f"(d1), "+f"(d2), "+f"(d3)
        : "r"(a0), "r"(a1), "r"(a2), "r"(a3), "r"(b0), "r"(b1));
}
#define CP_ASYNC16(dst_u32, src_ptr) \
    asm volatile("cp.async.ca.shared.global [%0], [%1], 16;" \
                 :: "r"(dst_u32), "l"(src_ptr))
#define CP_COMMIT()  asm volatile("cp.async.commit_group;")
#define CP_WAIT0()   asm volatile("cp.async.wait_group 0;")

// ---------------------------------------------------------------------------
// bf16x3 GEMM (R12 config, BK=16): C[M,N] = A[M,K] @ W[K,N] + bias.
// BM=128, BN=64. 256 threads = 8 warps (4m x 2n), warp tile m32 x n32.
// ---------------------------------------------------------------------------
__global__ __launch_bounds__(256, 2) void gemm_bias_kernel(
    const float* __restrict__ A, const float* __restrict__ W,
    const float* __restrict__ bias, float* __restrict__ C,
    int M, int N, int K)
{
    __shared__ unsigned Ah[8 * 136];  // [kpair][m] bf16x2
    __shared__ unsigned Al[8 * 136];
    __shared__ unsigned Bh[8 * 72];   // [kpair][n] bf16x2
    __shared__ unsigned Bl[8 * 72];

    int bm = blockIdx.y * 128;
    int bn = blockIdx.x * 64;
    int tid = threadIdx.x;
    int warp = tid >> 5, lane = tid & 31;
    int wm = warp >> 1, wn = warp & 1;
    int lq = lane >> 2, lr = lane & 3;

    float acc[2][4][4];
#pragma unroll
    for (int mt = 0; mt < 2; mt++)
#pragma unroll
        for (int nt = 0; nt < 4; nt++)
#pragma unroll
            for (int c = 0; c < 4; c++) acc[mt][nt][c] = 0.f;

    int am = tid >> 1, akp = (tid & 1) * 4;
    int bk2 = tid >> 5, bc2 = (tid & 31) * 2;

    const float* Ap  = A + (size_t)(bm + am) * K + akp * 2;
    const float* Wp0 = W + (size_t)(2 * bk2) * N + bn + bc2;
    const float* Wp1 = W + (size_t)(2 * bk2 + 1) * N + bn + bc2;

    float4 a0v = *(const float4*)(Ap);
    float4 a1v = *(const float4*)(Ap + 4);
    float2 w0v = *(const float2*)(Wp0);
    float2 w1v = *(const float2*)(Wp1);

    for (int k0 = 0; k0 < K; k0 += 16) {
        __syncthreads();
        {
            float av[8] = {a0v.x, a0v.y, a0v.z, a0v.w, a1v.x, a1v.y, a1v.z, a1v.w};
#pragma unroll
            for (int c = 0; c < 4; c++) {
                unsigned h, l;
                split2_bf16(av[2 * c], av[2 * c + 1], h, l);
                Ah[(akp + c) * 136 + am] = h;
                Al[(akp + c) * 136 + am] = l;
            }
            unsigned h0, l0, h1, l1;
            split2_bf16(w0v.x, w1v.x, h0, l0);
            split2_bf16(w0v.y, w1v.y, h1, l1);
            Bh[bk2 * 72 + bc2]     = h0;
            Bl[bk2 * 72 + bc2]     = l0;
            Bh[bk2 * 72 + bc2 + 1] = h1;
            Bl[bk2 * 72 + bc2 + 1] = l1;
        }
        __syncthreads();

        if (k0 + 16 < K) {
            a0v = *(const float4*)(Ap + k0 + 16);
            a1v = *(const float4*)(Ap + k0 + 20);
            w0v = *(const float2*)(Wp0 + (size_t)(k0 + 16) * N);
            w1v = *(const float2*)(Wp1 + (size_t)(k0 + 16) * N);
        }

        unsigned ah[2][4], al_[2][4];
#pragma unroll
        for (int mt = 0; mt < 2; mt++) {
            int mb = wm * 32 + mt * 16 + lq;
            ah[mt][0]  = Ah[lr * 136 + mb];
            ah[mt][1]  = Ah[lr * 136 + mb + 8];
            ah[mt][2]  = Ah[(lr + 4) * 136 + mb];
            ah[mt][3]  = Ah[(lr + 4) * 136 + mb + 8];
            al_[mt][0] = Al[lr * 136 + mb];
            al_[mt][1] = Al[lr * 136 + mb + 8];
            al_[mt][2] = Al[(lr + 4) * 136 + mb];
            al_[mt][3] = Al[(lr + 4) * 136 + mb + 8];
        }
#pragma unroll
        for (int nt = 0; nt < 4; nt++) {
            int nb = wn * 32 + nt * 8 + lq;
            unsigned bh0 = Bh[lr * 72 + nb];
            unsigned bh1 = Bh[(lr + 4) * 72 + nb];
            unsigned bl0 = Bl[lr * 72 + nb];
            unsigned bl1 = Bl[(lr + 4) * 72 + nb];
#pragma unroll
            for (int mt = 0; mt < 2; mt++) {
                mma_bf16(acc[mt][nt][0], acc[mt][nt][1], acc[mt][nt][2], acc[mt][nt][3],
                         ah[mt][0], ah[mt][1], ah[mt][2], ah[mt][3], bh0, bh1);
                mma_bf16(acc[mt][nt][0], acc[mt][nt][1], acc[mt][nt][2], acc[mt][nt][3],
                         ah[mt][0], ah[mt][1], ah[mt][2], ah[mt][3], bl0, bl1);
                mma_bf16(acc[mt][nt][0], acc[mt][nt][1], acc[mt][nt][2], acc[mt][nt][3],
                         al_[mt][0], al_[mt][1], al_[mt][2], al_[mt][3], bh0, bh1);
            }
        }
    }

#pragma unroll
    for (int mt = 0; mt < 2; mt++) {
        int row = bm + wm * 32 + mt * 16 + lq;
#pragma unroll
        for (int nt = 0; nt < 4; nt++) {
            int col = bn + wn * 32 + nt * 8 + 2 * lr;
            float bv0 = bias[col], bv1 = bias[col + 1];
            float2 o0, o1;
            o0.x = acc[mt][nt][0] + bv0; o0.y = acc[mt][nt][1] + bv1;
            o1.x = acc[mt][nt][2] + bv0; o1.y = acc[mt][nt][3] + bv1;
            *(float2*)&C[(size_t)row * N + col] = o0;
            *(float2*)&C[(size_t)(row + 8) * N + col] = o1;
        }
    }
}

// ---------------------------------------------------------------------------
// od kernel: warp per (b,t) row, w_od staged in smem.
// ---------------------------------------------------------------------------
__global__ __launch_bounds__(256) void od_kernel(
    const float* __restrict__ w_od, const float* __restrict__ b_od)
{
    __shared__ float ws[EE * 16];  // 32 KB
    int tid = threadIdx.x;
#pragma unroll
    for (int i = 0; i < 8; i++) {
        int idx = (i * 256 + tid) * 4;
        *(float4*)&ws[idx] = *(const float4*)&w_od[idx];
    }
    __syncthreads();

    int warp = tid >> 5, lane = tid & 31;
    int bt = blockIdx.x * 8 + warp;
    int b = bt / TT, t = bt % TT;
    const float* qrow = g_qkv + (size_t)bt * E3;

    int c = lane & 15, hseg = lane >> 4;
    float acc = 0.f;
#pragma unroll 8
    for (int kk = 0; kk < 256; kk++) {
        int k = 2 * kk + hseg;
        acc = fmaf(qrow[k], ws[k * 16 + c], acc);
    }
    acc += __shfl_xor_sync(0xffffffffu, acc, 16);
    float odm = acc + b_od[c];
    float odp = __shfl_sync(0xffffffffu, odm, (lane & 7) + 8);

    if (lane < 8) {
        int h = lane;
        float off = tanhf(odm) * (float)TT;
        float dur = (float)TT / (1.f + expf(-odp));
        float anchor = (float)t + off;
        float start = anchor - dur;
        float end   = anchor + dur;
        float blv = floorf(start);
        float brv = ceilf(end);
        float alv = floorf(anchor);
        float frv = anchor - alv;
        float* p = g_params + ((size_t)(b * NHH + h) * TT + t) * 6;
        p[0] = blv;
        p[1] = brv;
        p[2] = blv - start;
        p[3] = end - brv;
        p[4] = alv;
        p[5] = frv;
    }
}

// ---------------------------------------------------------------------------
// Tensor-core flash deformable attention, shift-free softmax + cp.async.
// K: cp.async raw fp32 into double-buffered operand smem (raw fp32 bits used
//    as truncated tf32 directly by the MMA).
// V: cp.async raw into a staging buffer; hi/lo bf16 split done smem->smem.
// Next tile's cp.async overlaps QK/softmax/PV of the current tile.
// ---------------------------------------------------------------------------
#define QS_S 68
#define VS_S 72
__global__ __launch_bounds__(256, 2) void attn_kernel()
{
    extern __shared__ unsigned smu[];
    unsigned* Qs  = smu;                   // [128 q][QS_S] tf32; reused as P (fp32)
    float*   Psf  = (float*)smu;           // overlay
    unsigned* Ks  = Qs + 128 * QS_S;       // [2][64 j][QS_S] raw fp32 (tf32-trunc)
    unsigned* Vst = Ks + 2 * 64 * QS_S;    // [64 j][QS_S] raw fp32 staging
    unsigned* Vh  = Vst + 64 * QS_S;       // [32 jpair][VS_S] bf16x2 hi
    unsigned* Vl  = Vh + 32 * VS_S;        // [32 jpair][VS_S] bf16x2 lo
    float*    Pp  = (float*)(Vl + 32 * VS_S); // [128][8] params
    __shared__ int s_jt0, s_jt1;

    int qt = blockIdx.x;
    int bh = blockIdx.y;
    int b = bh >> 3, h = bh & 7;
    int tid = threadIdx.x;
    int warp = tid >> 5, lane = tid & 31;
    int lq = lane >> 2, lr = lane & 3;
    int q0 = qt * 128;

    // Q fill (tf32, pre-scaled by SCALE*log2e)
    const float* qbase = g_qkv + ((size_t)(b * TT) + q0) * E3 + h * HDD;
#pragma unroll
    for (int it = 0; it < 8; it++) {
        int idx = it * 256 + tid;
        int r = idx >> 4, c4 = idx & 15;
        float4 v = *(const float4*)&qbase[(size_t)r * E3 + c4 * 4];
        uint4 u;
        u.x = f2tf32(v.x * QSC); u.y = f2tf32(v.y * QSC);
        u.z = f2tf32(v.z * QSC); u.w = f2tf32(v.w * QSC);
        *(uint4*)&Qs[r * QS_S + c4 * 4] = u;
    }
    // params
    if (tid < 128) {
        const float* p = g_params + ((size_t)bh * TT + q0 + tid) * 6;
#pragma unroll
        for (int c = 0; c < 6; c++) Pp[tid * 8 + c] = p[c];
        float lo = fmaxf(p[0], 0.f);
        float hi = fminf(p[1], (float)(TT - 1));
        Pp[tid * 8 + 6] = lo;
        Pp[tid * 8 + 7] = hi;
    }
    __syncthreads();
    if (tid == 0) {
        float jmin = 1e30f, jmax = -1e30f;
        int empty = 0;
        for (int r = 0; r < 128; r++) {
            float lo = Pp[r * 8 + 6], hi = Pp[r * 8 + 7];
            if (lo > hi) empty = 1;
            jmin = fminf(jmin, lo);
            jmax = fmaxf(jmax, hi);
        }
        if (empty) { s_jt0 = 0; s_jt1 = TT - 1; }
        else       { s_jt0 = ((int)jmin) & ~63; s_jt1 = (int)jmax; }
    }
    __syncthreads();

    int lr0 = warp * 16 + lq;
    int lr1 = lr0 + 8;
    float bl0 = Pp[lr0 * 8 + 0], br0 = Pp[lr0 * 8 + 1];
    float wbl0 = Pp[lr0 * 8 + 2], wbr0 = Pp[lr0 * 8 + 3];
    float al0 = Pp[lr0 * 8 + 4], fr0 = Pp[lr0 * 8 + 5];
    float bl1 = Pp[lr1 * 8 + 0], br1 = Pp[lr1 * 8 + 1];
    float wbl1 = Pp[lr1 * 8 + 2], wbr1 = Pp[lr1 * 8 + 3];
    float al1 = Pp[lr1 * 8 + 4], fr1 = Pp[lr1 * 8 + 5];
    float fa0 = 1.f - fr0, ar0 = al0 + 1.f;
    float fa1 = 1.f - fr1, ar1 = al1 + 1.f;

    // Q a-frags (persistent; smem Q is overwritten by P later)
    unsigned qa[8][4];
#pragma unroll
    for (int kt = 0; kt < 8; kt++) {
        qa[kt][0] = Qs[lr0 * QS_S + kt * 8 + lr];
        qa[kt][1] = Qs[lr1 * QS_S + kt * 8 + lr];
        qa[kt][2] = Qs[lr0 * QS_S + kt * 8 + lr + 4];
        qa[kt][3] = Qs[lr1 * QS_S + kt * 8 + lr + 4];
    }

    float l0 = 0.f, l1 = 0.f;
    float o[8][4];
#pragma unroll
    for (int nt = 0; nt < 8; nt++)
#pragma unroll
        for (int c = 0; c < 4; c++) o[nt][c] = 0.f;

    const float* kbase = g_qkv + (size_t)(b * TT) * E3 + EE + h * HDD;
    const float* vbase = g_qkv + (size_t)(b * TT) * E3 + 2 * EE + h * HDD;
    int jt0 = s_jt0, jt1 = s_jt1;

    // cp.async target addresses (per-thread fixed offsets)
    int cr = tid >> 4, cc4 = (tid & 15) * 4;   // row block base, col
    unsigned ks_addr0 = (unsigned)__cvta_generic_to_shared(&Ks[cr * QS_S + cc4]);
    unsigned ks_addr1 = (unsigned)__cvta_generic_to_shared(&Ks[64 * QS_S + cr * QS_S + cc4]);
    unsigned vst_addr = (unsigned)__cvta_generic_to_shared(&Vst[cr * QS_S + cc4]);
    const float* ksrc = kbase + (size_t)cr * E3 + cc4;
    const float* vsrc = vbase + (size_t)cr * E3 + cc4;

    // prologue: async-load tile jt0 into buffer 0
    {
#pragma unroll
        for (int it = 0; it < 4; it++) {
            size_t goff = (size_t)(jt0 + it * 16) * E3;
            CP_ASYNC16(ks_addr0 + it * 16 * QS_S * 4, ksrc + goff);
            CP_ASYNC16(vst_addr + it * 16 * QS_S * 4, vsrc + goff);
        }
        CP_COMMIT();
    }

    int buf = 0;
    for (int jt = jt0; jt <= jt1; jt += 64) {
        CP_WAIT0();
        __syncthreads();
        // convert V staging -> Vh/Vl (smem -> smem, no LDG on critical path)
        {
            int r2 = tid >> 3, c8 = (tid & 7) * 8;  // jpair r2, cols c8..c8+7
            const float* v0p = (const float*)&Vst[(2 * r2) * QS_S + c8];
            const float* v1p = (const float*)&Vst[(2 * r2 + 1) * QS_S + c8];
            float4 v0a = *(const float4*)(v0p);
            float4 v0b = *(const float4*)(v0p + 4);
            float4 v1a = *(const float4*)(v1p);
            float4 v1b = *(const float4*)(v1p + 4);
            float r0v[8] = {v0a.x, v0a.y, v0a.z, v0a.w, v0b.x, v0b.y, v0b.z, v0b.w};
            float r1v[8] = {v1a.x, v1a.y, v1a.z, v1a.w, v1b.x, v1b.y, v1b.z, v1b.w};
#pragma unroll
            for (int cc = 0; cc < 8; cc++) {
                unsigned hv, lv;
                split2_bf16(r0v[cc], r1v[cc], hv, lv);
                Vh[r2 * VS_S + c8 + cc] = hv;
                Vl[r2 * VS_S + c8 + cc] = lv;
            }
        }
        __syncthreads();
        // issue next tile's async loads (overlaps QK/softmax/PV below)
        int jn = jt + 64;
        if (jn <= jt1) {
            unsigned kdst = buf ? ks_addr0 : ks_addr1;
#pragma unroll
            for (int it = 0; it < 4; it++) {
                size_t goff = (size_t)(jn + it * 16) * E3;
                CP_ASYNC16(kdst + it * 16 * QS_S * 4, ksrc + goff);
                CP_ASYNC16(vst_addr + it * 16 * QS_S * 4, vsrc + goff);
            }
            CP_COMMIT();
        }

        const unsigned* Kb = Ks + buf * 64 * QS_S;

        // S = Q @ K^T (tf32; raw fp32 K = truncated tf32; output in log2 units)
        float s[8][4];
#pragma unroll
        for (int nt = 0; nt < 8; nt++)
#pragma unroll
            for (int c = 0; c < 4; c++) s[nt][c] = 0.f;
#pragma unroll
        for (int kt = 0; kt < 8; kt++) {
#pragma unroll
            for (int nt = 0; nt < 8; nt++) {
                unsigned b0 = Kb[(nt * 8 + lq) * QS_S + kt * 8 + lr];
                unsigned b1 = Kb[(nt * 8 + lq) * QS_S + kt * 8 + lr + 4];
                mma_tf32(s[nt][0], s[nt][1], s[nt][2], s[nt][3],
                         qa[kt][0], qa[kt][1], qa[kt][2], qa[kt][3], b0, b1);
            }
        }

        // weights + mask + exp2 (no shift; masked -> EPS)
#pragma unroll
        for (int nt = 0; nt < 8; nt++) {
            float jf0 = (float)(jt + nt * 8 + 2 * lr);
            float jf1 = jf0 + 1.f;
            float p0, p1, p2, p3;
            {
                float w = 1.f;
                if (jf0 == bl0) w += wbl0;
                if (jf0 == br0) w += wbr0;
                if (jf0 == al0) w += fa0;
                if (jf0 == ar0) w += fr0;
                p0 = (jf0 < bl0 || jf0 > br0) ? MASK_EPS : exp2f(s[nt][0] * w);
            }
            {
                float w = 1.f;
                if (jf1 == bl0) w += wbl0;
                if (jf1 == br0) w += wbr0;
                if (jf1 == al0) w += fa0;
                if (jf1 == ar0) w += fr0;
                p1 = (jf1 < bl0 || jf1 > br0) ? MASK_EPS : exp2f(s[nt][1] * w);
            }
            {
                float w = 1.f;
                if (jf0 == bl1) w += wbl1;
                if (jf0 == br1) w += wbr1;
                if (jf0 == al1) w += fa1;
                if (jf0 == ar1) w += fr1;
                p2 = (jf0 < bl1 || jf0 > br1) ? MASK_EPS : exp2f(s[nt][2] * w);
            }
            {
                float w = 1.f;
                if (jf1 == bl1) w += wbl1;
                if (jf1 == br1) w += wbr1;
                if (jf1 == al1) w += fa1;
                if (jf1 == ar1) w += fr1;
                p3 = (jf1 < bl1 || jf1 > br1) ? MASK_EPS : exp2f(s[nt][3] * w);
            }
            l0 += p0 + p1;
            l1 += p2 + p3;
            float2 w0; w0.x = p0; w0.y = p1;
            float2 w1; w1.x = p2; w1.y = p3;
            *(float2*)&Psf[lr0 * QS_S + nt * 8 + 2 * lr] = w0;
            *(float2*)&Psf[lr1 * QS_S + nt * 8 + 2 * lr] = w1;
        }
        __syncwarp();

        // O += P @ V (bf16x3, interleaved products)
#pragma unroll
        for (int kt = 0; kt < 4; kt++) {
            float2 p0 = *(const float2*)&Psf[lr0 * QS_S + kt * 16 + 2 * lr];
            float2 p1 = *(const float2*)&Psf[lr1 * QS_S + kt * 16 + 2 * lr];
            float2 p2 = *(const float2*)&Psf[lr0 * QS_S + kt * 16 + 8 + 2 * lr];
            float2 p3 = *(const float2*)&Psf[lr1 * QS_S + kt * 16 + 8 + 2 * lr];
            unsigned ph0, pl0, ph1, pl1, ph2, pl2, ph3, pl3;
            split2_bf16(p0.x, p0.y, ph0, pl0);
            split2_bf16(p1.x, p1.y, ph1, pl1);
            split2_bf16(p2.x, p2.y, ph2, pl2);
            split2_bf16(p3.x, p3.y, ph3, pl3);
#pragma unroll
            for (int nt = 0; nt < 8; nt++) {
                int nb = nt * 8 + lq;
                unsigned bh0 = Vh[(kt * 8 + lr) * VS_S + nb];
                unsigned bh1 = Vh[(kt * 8 + lr + 4) * VS_S + nb];
                unsigned bl0v = Vl[(kt * 8 + lr) * VS_S + nb];
                unsigned bl1v = Vl[(kt * 8 + lr + 4) * VS_S + nb];
                mma_bf16(o[nt][0], o[nt][1], o[nt][2], o[nt][3],
                         ph0, ph1, ph2, ph3, bh0, bh1);
                mma_bf16(o[nt][0], o[nt][1], o[nt][2], o[nt][3],
                         ph0, ph1, ph2, ph3, bl0v, bl1v);
                mma_bf16(o[nt][0], o[nt][1], o[nt][2], o[nt][3],
                         pl0, pl1, pl2, pl3, bh0, bh1);
            }
        }
        buf ^= 1;
    }

    // final row-sum reduction across the 4 threads of each row group
#pragma unroll
    for (int off = 1; off <= 2; off <<= 1) {
        l0 += __shfl_xor_sync(0xffffffffu, l0, off);
        l1 += __shfl_xor_sync(0xffffffffu, l1, off);
    }
    float inv0 = 1.f / l0, inv1 = 1.f / l1;
    float* ob = g_attn + ((size_t)(b * TT) + q0) * EE + h * HDD;
#pragma unroll
    for (int nt = 0; nt < 8; nt++) {
        int col = nt * 8 + 2 * lr;
        float2 v0, v1;
        v0.x = o[nt][0] * inv0; v0.y = o[nt][1] * inv0;
        v1.x = o[nt][2] * inv1; v1.y = o[nt][3] * inv1;
        *(float2*)&ob[(size_t)lr0 * EE + col] = v0;
        *(float2*)&ob[(size_t)lr1 * EE + col] = v1;
    }
}

#define ATTN_SMEM ((128*QS_S + 2*64*QS_S + 64*QS_S + 2*32*VS_S + 128*8) * 4)

// ---------------------------------------------------------------------------
extern "C" void kernel_launch(void* const* d_in, const int* in_sizes, int n_in,
                              void* d_out, int out_size)
{
    const float* x      = (const float*)d_in[0];
    const float* w_qkv  = (const float*)d_in[1];
    const float* b_qkv  = (const float*)d_in[2];
    const float* w_od   = (const float*)d_in[3];
    const float* b_od   = (const float*)d_in[4];
    const float* w_out  = (const float*)d_in[5];
    const float* b_out  = (const float*)d_in[6];
    float* out = (float*)d_out;

    float* qkv;  cudaGetSymbolAddress((void**)&qkv,  g_qkv);
    float* attn; cudaGetSymbolAddress((void**)&attn, g_attn);

    static int init = 0;
    if (!init) {
        init = 1;
        cudaFuncSetAttribute(attn_kernel,
                             cudaFuncAttributeMaxDynamicSharedMemorySize, ATTN_SMEM);
    }

    // 1) QKV = x @ w_qkv + b_qkv : bf16x3, BK=16
    gemm_bias_kernel<<<dim3(E3 / 64, (BB * TT) / 128), 256>>>(
        x, w_qkv, b_qkv, qkv, BB * TT, E3, EE);

    // 2) window params (fp32)
    od_kernel<<<(BB * TT) / 8, 256>>>(w_od, b_od);

    // 3) tensor-core flash deformable attention (cp.async pipelined)
    attn_kernel<<<dim3(TT / 128, BHH), 256, ATTN_SMEM>>>();

    // 4) out = attn @ w_out + b_out : bf16x3, BK=16
    gemm_bias_kernel<<<dim3(EE / 64, (BB * TT) / 128), 256>>>(
        attn, w_out, b_out, out, BB * TT, EE, EE);
}

// round 15
// speedup vs baseline: 1.1100x; 1.0735x over previous
#include <cuda_runtime.h>
#include <cuda_bf16.h>
#include <math.h>

#define BB 2
#define TT 2048
#define EE 512
#define NHH 8
#define HDD 64
#define BHH (BB*NHH)
#define E3 (3*EE)
// SCALE * log2(e): folded into Q at fill time -> QK output is in log2 units
#define QSC 0.18033688011112042f
// EPS for masked columns: 2^-60. All-masked rows normalize to exactly 1/T.
#define MASK_EPS 0x1.0p-60f

// Scratch (no allocations allowed)
__device__ float g_qkv[(size_t)BB * TT * E3];    // 25 MB
__device__ float g_params[(size_t)BHH * TT * 6];
__device__ float g_attn[(size_t)BB * TT * EE];   // 8 MB

// ---------------------------------------------------------------------------
// helpers
// ---------------------------------------------------------------------------
__device__ __forceinline__ unsigned f2tf32(float x) {
    unsigned r; asm("cvt.rna.tf32.f32 %0, %1;" : "=r"(r) : "f"(x)); return r;
}
__device__ __forceinline__ void split2_bf16(float x, float y, unsigned& h, unsigned& l) {
    __nv_bfloat16 hx = __float2bfloat16(x);
    __nv_bfloat16 hy = __float2bfloat16(y);
    float rx = x - __bfloat162float(hx);
    float ry = y - __bfloat162float(hy);
    __nv_bfloat16 lx = __float2bfloat16(rx);
    __nv_bfloat16 ly = __float2bfloat16(ry);
    h = ((unsigned)__bfloat16_as_ushort(hy) << 16) | (unsigned)__bfloat16_as_ushort(hx);
    l = ((unsigned)__bfloat16_as_ushort(ly) << 16) | (unsigned)__bfloat16_as_ushort(lx);
}
__device__ __forceinline__ void mma_tf32(
    float& d0, float& d1, float& d2, float& d3,
    unsigned a0, unsigned a1, unsigned a2, unsigned a3,
    unsigned b0, unsigned b1)
{
    asm("mma.sync.aligned.m16n8k8.row.col.f32.tf32.tf32.f32 "
        "{%0,%1,%2,%3}, {%4,%5,%6,%7}, {%8,%9}, {%0,%1,%2,%3};"
        : "+f"(d0), "+f"(d1), "+f"(d2), "+f"(d3)
        : "r"(a0), "r"(a1), "r"(a2), "r"(a3), "r"(b0), "r"(b1));
}
__device__ __forceinline__ void mma_bf16(
    float& d0, float& d1, float& d2, float& d3,
    unsigned a0, unsigned a1, unsigned a2, unsigned a3,
    unsigned b0, unsigned b1)
{
    asm("mma.sync.aligned.m16n8k16.row.col.f32.bf16.bf16.f32 "
        "{%0,%1,%2,%3}, {%4,%5,%6,%7}, {%8,%9}, {%0,%1,%2,%3};"
        : "+f"(d0), "+f"(d1), "+f"(d2), "+f"(d3)
        : "r"(a0), "r"(a1), "r"(a2), "r"(a3), "r"(b0), "r"(b1));
}

// Sparse deformable-weight correction: for the <=4 special columns of this
// row that land in this 64-wide tile and inside the window, rebuild
// p = exp2(s * (1 + sum_delta)) from the stored p = exp2(s). Duplicate
// columns merge their deltas (matches the reference's additive weights).
__device__ __forceinline__ void apply_corrections(
    float* rowp, int jt, float bl, float br,
    float wbl, float wbr, float al, float fa, float fr, float& lacc)
{
    float cs[4] = {bl, br, al, al + 1.f};
    float ds[4] = {wbl, wbr, fa, fr};
    bool val[4];
    int ic[4];
#pragma unroll
    for (int i = 0; i < 4; i++) {
        float rel = cs[i] - (float)jt;
        val[i] = (rel >= 0.f) && (rel < 64.f) && (cs[i] >= bl) && (cs[i] <= br);
        ic[i] = (int)rel;
    }
#pragma unroll
    for (int i = 0; i < 4; i++) {
        if (val[i]) {
            float d = ds[i];
#pragma unroll
            for (int j2 = i + 1; j2 < 4; j2++) {
                if (val[j2] && ic[j2] == ic[i]) { d += ds[j2]; val[j2] = false; }
            }
            float p = rowp[ic[i]];
            float s = __log2f(p);
            float pn = exp2f(s * (1.f + d));
            rowp[ic[i]] = pn;
            lacc += pn - p;
        }
    }
}

// ---------------------------------------------------------------------------
// bf16x3 GEMM (R12 config, BK=16): C[M,N] = A[M,K] @ W[K,N] + bias.
// BM=128, BN=64. 256 threads = 8 warps (4m x 2n), warp tile m32 x n32.
// ---------------------------------------------------------------------------
__global__ __launch_bounds__(256, 2) void gemm_bias_kernel(
    const float* __restrict__ A, const float* __restrict__ W,
    const float* __restrict__ bias, float* __restrict__ C,
    int M, int N, int K)
{
    __shared__ unsigned Ah[8 * 136];  // [kpair][m] bf16x2
    __shared__ unsigned Al[8 * 136];
    __shared__ unsigned Bh[8 * 72];   // [kpair][n] bf16x2
    __shared__ unsigned Bl[8 * 72];

    int bm = blockIdx.y * 128;
    int bn = blockIdx.x * 64;
    int tid = threadIdx.x;
    int warp = tid >> 5, lane = tid & 31;
    int wm = warp >> 1, wn = warp & 1;
    int lq = lane >> 2, lr = lane & 3;

    float acc[2][4][4];
#pragma unroll
    for (int mt = 0; mt < 2; mt++)
#pragma unroll
        for (int nt = 0; nt < 4; nt++)
#pragma unroll
            for (int c = 0; c < 4; c++) acc[mt][nt][c] = 0.f;

    int am = tid >> 1, akp = (tid & 1) * 4;
    int bk2 = tid >> 5, bc2 = (tid & 31) * 2;

    const float* Ap  = A + (size_t)(bm + am) * K + akp * 2;
    const float* Wp0 = W + (size_t)(2 * bk2) * N + bn + bc2;
    const float* Wp1 = W + (size_t)(2 * bk2 + 1) * N + bn + bc2;

    float4 a0v = *(const float4*)(Ap);
    float4 a1v = *(const float4*)(Ap + 4);
    float2 w0v = *(const float2*)(Wp0);
    float2 w1v = *(const float2*)(Wp1);

    for (int k0 = 0; k0 < K; k0 += 16) {
        __syncthreads();
        {
            float av[8] = {a0v.x, a0v.y, a0v.z, a0v.w, a1v.x, a1v.y, a1v.z, a1v.w};
#pragma unroll
            for (int c = 0; c < 4; c++) {
                unsigned h, l;
                split2_bf16(av[2 * c], av[2 * c + 1], h, l);
                Ah[(akp + c) * 136 + am] = h;
                Al[(akp + c) * 136 + am] = l;
            }
            unsigned h0, l0, h1, l1;
            split2_bf16(w0v.x, w1v.x, h0, l0);
            split2_bf16(w0v.y, w1v.y, h1, l1);
            Bh[bk2 * 72 + bc2]     = h0;
            Bl[bk2 * 72 + bc2]     = l0;
            Bh[bk2 * 72 + bc2 + 1] = h1;
            Bl[bk2 * 72 + bc2 + 1] = l1;
        }
        __syncthreads();

        if (k0 + 16 < K) {
            a0v = *(const float4*)(Ap + k0 + 16);
            a1v = *(const float4*)(Ap + k0 + 20);
            w0v = *(const float2*)(Wp0 + (size_t)(k0 + 16) * N);
            w1v = *(const float2*)(Wp1 + (size_t)(k0 + 16) * N);
        }

        unsigned ah[2][4], al_[2][4];
#pragma unroll
        for (int mt = 0; mt < 2; mt++) {
            int mb = wm * 32 + mt * 16 + lq;
            ah[mt][0]  = Ah[lr * 136 + mb];
            ah[mt][1]  = Ah[lr * 136 + mb + 8];
            ah[mt][2]  = Ah[(lr + 4) * 136 + mb];
            ah[mt][3]  = Ah[(lr + 4) * 136 + mb + 8];
            al_[mt][0] = Al[lr * 136 + mb];
            al_[mt][1] = Al[lr * 136 + mb + 8];
            al_[mt][2] = Al[(lr + 4) * 136 + mb];
            al_[mt][3] = Al[(lr + 4) * 136 + mb + 8];
        }
#pragma unroll
        for (int nt = 0; nt < 4; nt++) {
            int nb = wn * 32 + nt * 8 + lq;
            unsigned bh0 = Bh[lr * 72 + nb];
            unsigned bh1 = Bh[(lr + 4) * 72 + nb];
            unsigned bl0 = Bl[lr * 72 + nb];
            unsigned bl1 = Bl[(lr + 4) * 72 + nb];
#pragma unroll
            for (int mt = 0; mt < 2; mt++) {
                mma_bf16(acc[mt][nt][0], acc[mt][nt][1], acc[mt][nt][2], acc[mt][nt][3],
                         ah[mt][0], ah[mt][1], ah[mt][2], ah[mt][3], bh0, bh1);
                mma_bf16(acc[mt][nt][0], acc[mt][nt][1], acc[mt][nt][2], acc[mt][nt][3],
                         ah[mt][0], ah[mt][1], ah[mt][2], ah[mt][3], bl0, bl1);
                mma_bf16(acc[mt][nt][0], acc[mt][nt][1], acc[mt][nt][2], acc[mt][nt][3],
                         al_[mt][0], al_[mt][1], al_[mt][2], al_[mt][3], bh0, bh1);
            }
        }
    }

#pragma unroll
    for (int mt = 0; mt < 2; mt++) {
        int row = bm + wm * 32 + mt * 16 + lq;
#pragma unroll
        for (int nt = 0; nt < 4; nt++) {
            int col = bn + wn * 32 + nt * 8 + 2 * lr;
            float bv0 = bias[col], bv1 = bias[col + 1];
            float2 o0, o1;
            o0.x = acc[mt][nt][0] + bv0; o0.y = acc[mt][nt][1] + bv1;
            o1.x = acc[mt][nt][2] + bv0; o1.y = acc[mt][nt][3] + bv1;
            *(float2*)&C[(size_t)row * N + col] = o0;
            *(float2*)&C[(size_t)(row + 8) * N + col] = o1;
        }
    }
}

// ---------------------------------------------------------------------------
// od kernel: warp per (b,t) row, w_od staged in smem.
// ---------------------------------------------------------------------------
__global__ __launch_bounds__(256) void od_kernel(
    const float* __restrict__ w_od, const float* __restrict__ b_od)
{
    __shared__ float ws[EE * 16];  // 32 KB
    int tid = threadIdx.x;
#pragma unroll
    for (int i = 0; i < 8; i++) {
        int idx = (i * 256 + tid) * 4;
        *(float4*)&ws[idx] = *(const float4*)&w_od[idx];
    }
    __syncthreads();

    int warp = tid >> 5, lane = tid & 31;
    int bt = blockIdx.x * 8 + warp;
    int b = bt / TT, t = bt % TT;
    const float* qrow = g_qkv + (size_t)bt * E3;

    int c = lane & 15, hseg = lane >> 4;
    float acc = 0.f;
#pragma unroll 8
    for (int kk = 0; kk < 256; kk++) {
        int k = 2 * kk + hseg;
        acc = fmaf(qrow[k], ws[k * 16 + c], acc);
    }
    acc += __shfl_xor_sync(0xffffffffu, acc, 16);
    float odm = acc + b_od[c];
    float odp = __shfl_sync(0xffffffffu, odm, (lane & 7) + 8);

    if (lane < 8) {
        int h = lane;
        float off = tanhf(odm) * (float)TT;
        float dur = (float)TT / (1.f + expf(-odp));
        float anchor = (float)t + off;
        float start = anchor - dur;
        float end   = anchor + dur;
        float blv = floorf(start);
        float brv = ceilf(end);
        float alv = floorf(anchor);
        float frv = anchor - alv;
        float* p = g_params + ((size_t)(b * NHH + h) * TT + t) * 6;
        p[0] = blv;
        p[1] = brv;
        p[2] = blv - start;
        p[3] = end - brv;
        p[4] = alv;
        p[5] = frv;
    }
}

// ---------------------------------------------------------------------------
// Tensor-core flash deformable attention, shift-free softmax with SPARSE
// deformable-weight corrections.
// Dense pass: p = masked ? EPS : exp2(s)  (no weight logic).
// Sparse pass: lane lr==0 of each quad fixes the <=4 special columns per row
// in smem and adjusts the quad's partial row-sum.
// QK: 1x tf32. PV: bf16x3 (R7 interleaved products).
// ---------------------------------------------------------------------------
#define QS_S 68
#define VS_S 72
__global__ __launch_bounds__(256, 2) void attn_kernel()
{
    extern __shared__ unsigned smu[];
    unsigned* Qs = smu;                  // [128 q][QS_S] tf32; reused as P (fp32)
    float*   Psf = (float*)smu;          // overlay
    unsigned* Ks = Qs + 128 * QS_S;      // [64 j][QS_S] tf32
    unsigned* Vh = Ks + 64 * QS_S;       // [32 jpair][VS_S] bf16x2 hi
    unsigned* Vl = Vh + 32 * VS_S;       // [32 jpair][VS_S] bf16x2 lo
    float*    Pp = (float*)(Vl + 32 * VS_S); // [128][8] params
    __shared__ int s_jt0, s_jt1;

    int qt = blockIdx.x;
    int bh = blockIdx.y;
    int b = bh >> 3, h = bh & 7;
    int tid = threadIdx.x;
    int warp = tid >> 5, lane = tid & 31;
    int lq = lane >> 2, lr = lane & 3;
    int q0 = qt * 128;

    // Q fill (tf32, pre-scaled by SCALE*log2e)
    const float* qbase = g_qkv + ((size_t)(b * TT) + q0) * E3 + h * HDD;
#pragma unroll
    for (int it = 0; it < 8; it++) {
        int idx = it * 256 + tid;
        int r = idx >> 4, c4 = idx & 15;
        float4 v = *(const float4*)&qbase[(size_t)r * E3 + c4 * 4];
        uint4 u;
        u.x = f2tf32(v.x * QSC); u.y = f2tf32(v.y * QSC);
        u.z = f2tf32(v.z * QSC); u.w = f2tf32(v.w * QSC);
        *(uint4*)&Qs[r * QS_S + c4 * 4] = u;
    }
    // params
    if (tid < 128) {
        const float* p = g_params + ((size_t)bh * TT + q0 + tid) * 6;
#pragma unroll
        for (int c = 0; c < 6; c++) Pp[tid * 8 + c] = p[c];
        float lo = fmaxf(p[0], 0.f);
        float hi = fminf(p[1], (float)(TT - 1));
        Pp[tid * 8 + 6] = lo;
        Pp[tid * 8 + 7] = hi;
    }
    __syncthreads();
    if (tid == 0) {
        float jmin = 1e30f, jmax = -1e30f;
        int empty = 0;
        for (int r = 0; r < 128; r++) {
            float lo = Pp[r * 8 + 6], hi = Pp[r * 8 + 7];
            if (lo > hi) empty = 1;
            jmin = fminf(jmin, lo);
            jmax = fmaxf(jmax, hi);
        }
        if (empty) { s_jt0 = 0; s_jt1 = TT - 1; }
        else       { s_jt0 = ((int)jmin) & ~63; s_jt1 = (int)jmax; }
    }
    __syncthreads();

    int lr0 = warp * 16 + lq;
    int lr1 = lr0 + 8;
    float bl0 = Pp[lr0 * 8 + 0], br0 = Pp[lr0 * 8 + 1];
    float wbl0 = Pp[lr0 * 8 + 2], wbr0 = Pp[lr0 * 8 + 3];
    float al0 = Pp[lr0 * 8 + 4], fr0 = Pp[lr0 * 8 + 5];
    float bl1 = Pp[lr1 * 8 + 0], br1 = Pp[lr1 * 8 + 1];
    float wbl1 = Pp[lr1 * 8 + 2], wbr1 = Pp[lr1 * 8 + 3];
    float al1 = Pp[lr1 * 8 + 4], fr1 = Pp[lr1 * 8 + 5];
    float fa0 = 1.f - fr0;
    float fa1 = 1.f - fr1;

    // Q a-frags (persistent; smem Q is overwritten by P later)
    unsigned qa[8][4];
#pragma unroll
    for (int kt = 0; kt < 8; kt++) {
        qa[kt][0] = Qs[lr0 * QS_S + kt * 8 + lr];
        qa[kt][1] = Qs[lr1 * QS_S + kt * 8 + lr];
        qa[kt][2] = Qs[lr0 * QS_S + kt * 8 + lr + 4];
        qa[kt][3] = Qs[lr1 * QS_S + kt * 8 + lr + 4];
    }

    float l0 = 0.f, l1 = 0.f;   // per-thread partial row sums
    float o[8][4];
#pragma unroll
    for (int nt = 0; nt < 8; nt++)
#pragma unroll
        for (int c = 0; c < 4; c++) o[nt][c] = 0.f;

    const float* kbase = g_qkv + (size_t)(b * TT) * E3 + EE + h * HDD;
    const float* vbase = g_qkv + (size_t)(b * TT) * E3 + 2 * EE + h * HDD;
    int jt0 = s_jt0, jt1 = s_jt1;

    for (int jt = jt0; jt <= jt1; jt += 64) {
        __syncthreads();
        // K fill (tf32 1x)
#pragma unroll
        for (int it = 0; it < 4; it++) {
            int idx = it * 256 + tid;
            int r = idx >> 4, c4 = idx & 15;
            float4 kv = *(const float4*)&kbase[(size_t)(jt + r) * E3 + c4 * 4];
            uint4 ku;
            ku.x = f2tf32(kv.x); ku.y = f2tf32(kv.y); ku.z = f2tf32(kv.z); ku.w = f2tf32(kv.w);
            *(uint4*)&Ks[r * QS_S + c4 * 4] = ku;
        }
        // V fill: bf16x2 packed across j pairs, hi/lo split
        {
            int r2 = tid >> 3, c8 = (tid & 7) * 8;
            const float* v0p = &vbase[(size_t)(jt + 2 * r2) * E3 + c8];
            const float* v1p = &vbase[(size_t)(jt + 2 * r2 + 1) * E3 + c8];
            float4 v0a = *(const float4*)(v0p);
            float4 v0b = *(const float4*)(v0p + 4);
            float4 v1a = *(const float4*)(v1p);
            float4 v1b = *(const float4*)(v1p + 4);
            float r0v[8] = {v0a.x, v0a.y, v0a.z, v0a.w, v0b.x, v0b.y, v0b.z, v0b.w};
            float r1v[8] = {v1a.x, v1a.y, v1a.z, v1a.w, v1b.x, v1b.y, v1b.z, v1b.w};
#pragma unroll
            for (int cc = 0; cc < 8; cc++) {
                unsigned hv, lv;
                split2_bf16(r0v[cc], r1v[cc], hv, lv);
                Vh[r2 * VS_S + c8 + cc] = hv;
                Vl[r2 * VS_S + c8 + cc] = lv;
            }
        }
        __syncthreads();

        // S = Q @ K^T (m16 x n64 per warp, tf32; output in log2 units)
        float s[8][4];
#pragma unroll
        for (int nt = 0; nt < 8; nt++)
#pragma unroll
            for (int c = 0; c < 4; c++) s[nt][c] = 0.f;
#pragma unroll
        for (int kt = 0; kt < 8; kt++) {
#pragma unroll
            for (int nt = 0; nt < 8; nt++) {
                unsigned b0 = Ks[(nt * 8 + lq) * QS_S + kt * 8 + lr];
                unsigned b1 = Ks[(nt * 8 + lq) * QS_S + kt * 8 + lr + 4];
                mma_tf32(s[nt][0], s[nt][1], s[nt][2], s[nt][3],
                         qa[kt][0], qa[kt][1], qa[kt][2], qa[kt][3], b0, b1);
            }
        }

        // dense pass: mask + exp2 only (weights handled sparsely below)
#pragma unroll
        for (int nt = 0; nt < 8; nt++) {
            float jf0 = (float)(jt + nt * 8 + 2 * lr);
            float jf1 = jf0 + 1.f;
            float p0 = (jf0 < bl0 || jf0 > br0) ? MASK_EPS : exp2f(s[nt][0]);
            float p1 = (jf1 < bl0 || jf1 > br0) ? MASK_EPS : exp2f(s[nt][1]);
            float p2 = (jf0 < bl1 || jf0 > br1) ? MASK_EPS : exp2f(s[nt][2]);
            float p3 = (jf1 < bl1 || jf1 > br1) ? MASK_EPS : exp2f(s[nt][3]);
            l0 += p0 + p1;
            l1 += p2 + p3;
            float2 w0; w0.x = p0; w0.y = p1;
            float2 w1; w1.x = p2; w1.y = p3;
            *(float2*)&Psf[lr0 * QS_S + nt * 8 + 2 * lr] = w0;
            *(float2*)&Psf[lr1 * QS_S + nt * 8 + 2 * lr] = w1;
        }
        __syncwarp();
        // sparse pass: one lane per quad fixes special columns of its 2 rows
        if (lr == 0) {
            apply_corrections(&Psf[lr0 * QS_S], jt, bl0, br0, wbl0, wbr0,
                              al0, fa0, fr0, l0);
            apply_corrections(&Psf[lr1 * QS_S], jt, bl1, br1, wbl1, wbr1,
                              al1, fa1, fr1, l1);
        }
        __syncwarp();

        // O += P @ V (bf16x3, interleaved products)
#pragma unroll
        for (int kt = 0; kt < 4; kt++) {
            float2 p0 = *(const float2*)&Psf[lr0 * QS_S + kt * 16 + 2 * lr];
            float2 p1 = *(const float2*)&Psf[lr1 * QS_S + kt * 16 + 2 * lr];
            float2 p2 = *(const float2*)&Psf[lr0 * QS_S + kt * 16 + 8 + 2 * lr];
            float2 p3 = *(const float2*)&Psf[lr1 * QS_S + kt * 16 + 8 + 2 * lr];
            unsigned ph0, pl0, ph1, pl1, ph2, pl2, ph3, pl3;
            split2_bf16(p0.x, p0.y, ph0, pl0);
            split2_bf16(p1.x, p1.y, ph1, pl1);
            split2_bf16(p2.x, p2.y, ph2, pl2);
            split2_bf16(p3.x, p3.y, ph3, pl3);
#pragma unroll
            for (int nt = 0; nt < 8; nt++) {
                int nb = nt * 8 + lq;
                unsigned bh0 = Vh[(kt * 8 + lr) * VS_S + nb];
                unsigned bh1 = Vh[(kt * 8 + lr + 4) * VS_S + nb];
                unsigned bl0v = Vl[(kt * 8 + lr) * VS_S + nb];
                unsigned bl1v = Vl[(kt * 8 + lr + 4) * VS_S + nb];
                mma_bf16(o[nt][0], o[nt][1], o[nt][2], o[nt][3],
                         ph0, ph1, ph2, ph3, bh0, bh1);
                mma_bf16(o[nt][0], o[nt][1], o[nt][2], o[nt][3],
                         ph0, ph1, ph2, ph3, bl0v, bl1v);
                mma_bf16(o[nt][0], o[nt][1], o[nt][2], o[nt][3],
                         pl0, pl1, pl2, pl3, bh0, bh1);
            }
        }
    }

    // final row-sum reduction across the 4 threads of each row group
#pragma unroll
    for (int off = 1; off <= 2; off <<= 1) {
        l0 += __shfl_xor_sync(0xffffffffu, l0, off);
        l1 += __shfl_xor_sync(0xffffffffu, l1, off);
    }
    float inv0 = 1.f / l0, inv1 = 1.f / l1;
    float* ob = g_attn + ((size_t)(b * TT) + q0) * EE + h * HDD;
#pragma unroll
    for (int nt = 0; nt < 8; nt++) {
        int col = nt * 8 + 2 * lr;
        float2 v0, v1;
        v0.x = o[nt][0] * inv0; v0.y = o[nt][1] * inv0;
        v1.x = o[nt][2] * inv1; v1.y = o[nt][3] * inv1;
        *(float2*)&ob[(size_t)lr0 * EE + col] = v0;
        *(float2*)&ob[(size_t)lr1 * EE + col] = v1;
    }
}

#define ATTN_SMEM ((128*QS_S + 64*QS_S + 2*32*VS_S + 128*8) * 4)

// ---------------------------------------------------------------------------
extern "C" void kernel_launch(void* const* d_in, const int* in_sizes, int n_in,
                              void* d_out, int out_size)
{
    const float* x      = (const float*)d_in[0];
    const float* w_qkv  = (const float*)d_in[1];
    const float* b_qkv  = (const float*)d_in[2];
    const float* w_od   = (const float*)d_in[3];
    const float* b_od   = (const float*)d_in[4];
    const float* w_out  = (const float*)d_in[5];
    const float* b_out  = (const float*)d_in[6];
    float* out = (float*)d_out;

    float* qkv;  cudaGetSymbolAddress((void**)&qkv,  g_qkv);
    float* attn; cudaGetSymbolAddress((void**)&attn, g_attn);

    static int init = 0;
    if (!init) {
        init = 1;
        cudaFuncSetAttribute(attn_kernel,
                             cudaFuncAttributeMaxDynamicSharedMemorySize, ATTN_SMEM);
    }

    // 1) QKV = x @ w_qkv + b_qkv : bf16x3, BK=16
    gemm_bias_kernel<<<dim3(E3 / 64, (BB * TT) / 128), 256>>>(
        x, w_qkv, b_qkv, qkv, BB * TT, E3, EE);

    // 2) window params (fp32)
    od_kernel<<<(BB * TT) / 8, 256>>>(w_od, b_od);

    // 3) tensor-core flash deformable attention (sparse-corrected softmax)
    attn_kernel<<<dim3(TT / 128, BHH), 256, ATTN_SMEM>>>();

    // 4) out = attn @ w_out + b_out : bf16x3, BK=16
    gemm_bias_kernel<<<dim3(EE / 64, (BB * TT) / 128), 256>>>(
        attn, w_out, b_out, out, BB * TT, EE, EE);
}